// round 14
// baseline (speedup 1.0000x reference)
#include <cuda_runtime.h>
#include <cstdint>

// ============================================================================
// BESNumEigen3qubitModel — analytic restructuring + task-pair-packed Jacobi.
// 3 Hermitian 8x8 eigenproblems per batch element (rho, pt_a, pt_c);
// dm0/dm1 eigenvalues are affine maps beta*(w - 1/8) + 1/8 of rho's.
//
// R14: f32x2 lanes now hold TWO INDEPENDENT TASKS (lo=task A, hi=task B),
// with separate packed re (mr) and im (mi) arrays. Complex rotation updates
// become lane-independent scalar-complex math: zero cross-lane swaps, zero
// conj XOR fixups (conjugation = compile-time sign patterns baked into 5
// pre-negated packed coefficients). Angle chains are ILP-2 across lanes.
// ============================================================================

#define BMAX 32768

__device__ float g_eigs[3 * BMAX * 8];

using u64 = unsigned long long;

static constexpr u64 SGN2 = 0x8000000080000000ULL;  // negate both lanes

// ---------------------------------------------------------------------------
// packed f32x2 helpers
// ---------------------------------------------------------------------------
__device__ __forceinline__ u64 pk2(float lo, float hi) {
    u64 r; asm("mov.b64 %0, {%1, %2};" : "=l"(r) : "f"(lo), "f"(hi)); return r;
}
__device__ __forceinline__ void upk2(u64 v, float& lo, float& hi) {
    asm("mov.b64 {%0, %1}, %2;" : "=f"(lo), "=f"(hi) : "l"(v));
}
__device__ __forceinline__ u64 f2fma(u64 a, u64 b, u64 c) {
    u64 r; asm("fma.rn.f32x2 %0, %1, %2, %3;" : "=l"(r) : "l"(a), "l"(b), "l"(c));
    return r;
}
__device__ __forceinline__ u64 f2mul(u64 a, u64 b) {
    u64 r; asm("mul.rn.f32x2 %0, %1, %2;" : "=l"(r) : "l"(a), "l"(b));
    return r;
}

// upper-triangle linear index for j<k
__host__ __device__ constexpr int uidx(int j, int k) {
    return 7 * j - (j * (j - 1)) / 2 + (k - j - 1);
}

// ---------------------------------------------------------------------------
// partial-transpose index permutations (applied at build time)
// pt_a swaps the 'a' bit (4), pt_c swaps the 'c' bit (1). Diagonal fixed.
// ---------------------------------------------------------------------------
__host__ __device__ constexpr int permR(int TYPE, int j, int k) {
    return TYPE == 0 ? j : (TYPE == 1 ? ((j & 3) | (k & 4)) : ((j & 6) | (k & 1)));
}
__host__ __device__ constexpr int permC(int TYPE, int j, int k) {
    return TYPE == 0 ? k : (TYPE == 1 ? ((k & 3) | (j & 4)) : ((k & 6) | (j & 1)));
}

// ---------------------------------------------------------------------------
// Build: packed upper triangle (mr = re, mi = im; lanes = two tasks) + scalar
// diagonals dA/dB from two coefficient vectors v0 (lane lo) and v1 (lane hi).
// v layout: [0..27] symmetric pairs, [28..55] antisymmetric, [56..62] diag.
// ---------------------------------------------------------------------------
template <int TYPE>
__device__ __forceinline__ void build8(const float* __restrict__ v0,
                                       const float* __restrict__ v1,
                                       u64 mr[28], u64 mi[28],
                                       float dA[8], float dB[8]) {
    const float COEF[7] = {
        1.0f, 0.5773502691896258f, 0.4082482904638631f, 0.31622776601683794f,
        0.2581988897471611f, 0.21821789023599236f, 0.1889822365046136f
    };

    float ssA = 0.f, ssB = 0.f;
    float ddA[8], ddB[8];
#pragma unroll
    for (int j = 0; j < 8; ++j) { ddA[j] = 0.f; ddB[j] = 0.f; }

#pragma unroll
    for (int l = 1; l <= 7; ++l) {
        float xA = v0[55 + l], xB = v1[55 + l];
        ssA += xA * xA; ssB += xB * xB;
        xA *= COEF[l - 1]; xB *= COEF[l - 1];
#pragma unroll
        for (int j = 0; j < 7; ++j)
            if (j < l) { ddA[j] += xA; ddB[j] += xB; }
        ddA[l] -= (float)l * xA;
        ddB[l] -= (float)l * xB;
    }

#pragma unroll
    for (int j = 0; j < 8; ++j) {
#pragma unroll
        for (int k = j + 1; k < 8; ++k) {
            const int p = uidx(j, k);
            float vsA = v0[p], vaA = v0[28 + p];
            float vsB = v1[p], vaB = v1[28 + p];
            ssA += vsA * vsA + vaA * vaA;
            ssB += vsB * vsB + vaB * vaB;
            // element at permuted (R,C) is vs - i*va; mirror is conjugate
            const int R = permR(TYPE, j, k), C = permC(TYPE, j, k);
            if (R < C) {
                mr[uidx(R, C)] = pk2(vsA, vsB);
                mi[uidx(R, C)] = pk2(-vaA, -vaB);
            } else {
                mr[uidx(C, R)] = pk2(vsA, vsB);
                mi[uidx(C, R)] = pk2(vaA, vaB);
            }
        }
    }

    float invA = rsqrtf(ssA), invB = rsqrtf(ssB);
    u64 inv2 = pk2(invA, invB);
#pragma unroll
    for (int i = 0; i < 28; ++i) {
        mr[i] = f2mul(mr[i], inv2);
        mi[i] = f2mul(mi[i], inv2);
    }
#pragma unroll
    for (int j = 0; j < 8; ++j) {
        dA[j] = 0.125f + ddA[j] * invA;
        dB[j] = 0.125f + ddB[j] * invB;
    }
}

// ---------------------------------------------------------------------------
// Spectator update for pivot (P,Q), one spectator element pair.
// CASE 0: k<P (both stored direct)
// CASE 1: P<k<Q (p-side stored conjugated)
// CASE 2: k>Q (both stored conjugated)
// Sign patterns derived from  A'[k][P] = c*A[k][P] - conj(su)*A[k][Q],
//                             A'[k][Q] = su*A[k][P] + c*A[k][Q].
// ---------------------------------------------------------------------------
template <int CASE>
__device__ __forceinline__ void upd(u64& zpr, u64& zpi, u64& zqr, u64& zqi,
                                    u64 c2, u64 scr2, u64 nscr2,
                                    u64 sci2, u64 nsci2) {
    u64 npr, npi, nqr, nqi;
    if (CASE == 0) {
        npr = f2fma(nsci2, zqi, f2fma(nscr2, zqr, f2mul(c2, zpr)));
        npi = f2fma( sci2, zqr, f2fma(nscr2, zqi, f2mul(c2, zpi)));
        nqr = f2fma(nsci2, zpi, f2fma( scr2, zpr, f2mul(c2, zqr)));
        nqi = f2fma( sci2, zpr, f2fma( scr2, zpi, f2mul(c2, zqi)));
    } else if (CASE == 1) {
        npr = f2fma(nsci2, zqi, f2fma(nscr2, zqr, f2mul(c2, zpr)));
        npi = f2fma(nsci2, zqr, f2fma( scr2, zqi, f2mul(c2, zpi)));
        nqr = f2fma( sci2, zpi, f2fma( scr2, zpr, f2mul(c2, zqr)));
        nqi = f2fma( sci2, zpr, f2fma(nscr2, zpi, f2mul(c2, zqi)));
    } else {
        npr = f2fma( sci2, zqi, f2fma(nscr2, zqr, f2mul(c2, zpr)));
        npi = f2fma(nsci2, zqr, f2fma(nscr2, zqi, f2mul(c2, zpi)));
        nqr = f2fma( sci2, zpi, f2fma( scr2, zpr, f2mul(c2, zqr)));
        nqi = f2fma(nsci2, zpr, f2fma( scr2, zpi, f2mul(c2, zqi)));
    }
    zpr = npr; zpi = npi; zqr = nqr; zqi = nqi;
}

// ---------------------------------------------------------------------------
// One pivot: per-lane scalar angle (ILP-2 MUFU chains), then 6 spectator
// updates in pure FFMA2 with pre-negated packed coefficients.
// ---------------------------------------------------------------------------
__device__ __forceinline__ void angle_lane(float r2, float dp, float dq,
                                           float& c, float& inv, float& tr) {
    float h = (dq - dp) * 0.5f;
    float hyp = sqrtf(h * h + r2);
    // den_safe: at r2=0,h=0 gives den=1e-20 -> c=1, s=0, tr=0 (identity).
    float den = h + copysignf(hyp, h);
    den = copysignf(fmaxf(fabsf(den), 1e-20f), den);
    inv = copysignf(rsqrtf(den * den + r2), den);
    c = den * inv;
    tr = __fdividef(r2, den);
}

template <int P, int Q>
__device__ __forceinline__ void pivot(u64 mr[28], u64 mi[28],
                                      float dA[8], float dB[8]) {
    const int I = uidx(P, Q);
    u64 xr = mr[I], xi = mi[I];
    u64 r2p = f2fma(xi, xi, f2mul(xr, xr));
    float r2a, r2b; upk2(r2p, r2a, r2b);

    float cA, invA, trA, cB, invB, trB;
    angle_lane(r2a, dA[P], dA[Q], cA, invA, trA);
    angle_lane(r2b, dB[P], dB[Q], cB, invB, trB);

    dA[P] -= trA; dA[Q] += trA;
    dB[P] -= trB; dB[Q] += trB;
    mr[I] = 0ULL; mi[I] = 0ULL;

    const u64 inv2  = pk2(invA, invB);
    const u64 c2    = pk2(cA, cB);
    const u64 scr2  = f2mul(xr, inv2);     // Re(s*u) per lane
    const u64 sci2  = f2mul(xi, inv2);     // Im(s*u) per lane
    const u64 nscr2 = scr2 ^ SGN2;
    const u64 nsci2 = sci2 ^ SGN2;

#pragma unroll
    for (int k = 0; k < 8; ++k) {
        if (k == P || k == Q) continue;
        if (k < P)
            upd<0>(mr[uidx(k, P)], mi[uidx(k, P)], mr[uidx(k, Q)], mi[uidx(k, Q)],
                   c2, scr2, nscr2, sci2, nsci2);
        else if (k > Q)
            upd<2>(mr[uidx(P, k)], mi[uidx(P, k)], mr[uidx(Q, k)], mi[uidx(Q, k)],
                   c2, scr2, nscr2, sci2, nsci2);
        else
            upd<1>(mr[uidx(P, k)], mi[uidx(P, k)], mr[uidx(k, Q)], mi[uidx(k, Q)],
                   c2, scr2, nscr2, sci2, nsci2);
    }
}

// ---------------------------------------------------------------------------
// One round-robin sweep: 28 pivots in tournament order.
// ---------------------------------------------------------------------------
__device__ __forceinline__ void jacobi_sweep(u64 mr[28], u64 mi[28],
                                             float dA[8], float dB[8]) {
    pivot<0,1>(mr,mi,dA,dB); pivot<2,7>(mr,mi,dA,dB); pivot<3,6>(mr,mi,dA,dB); pivot<4,5>(mr,mi,dA,dB);
    pivot<0,2>(mr,mi,dA,dB); pivot<1,3>(mr,mi,dA,dB); pivot<4,7>(mr,mi,dA,dB); pivot<5,6>(mr,mi,dA,dB);
    pivot<0,3>(mr,mi,dA,dB); pivot<2,4>(mr,mi,dA,dB); pivot<1,5>(mr,mi,dA,dB); pivot<6,7>(mr,mi,dA,dB);
    pivot<0,4>(mr,mi,dA,dB); pivot<3,5>(mr,mi,dA,dB); pivot<2,6>(mr,mi,dA,dB); pivot<1,7>(mr,mi,dA,dB);
    pivot<0,5>(mr,mi,dA,dB); pivot<4,6>(mr,mi,dA,dB); pivot<3,7>(mr,mi,dA,dB); pivot<1,2>(mr,mi,dA,dB);
    pivot<0,6>(mr,mi,dA,dB); pivot<5,7>(mr,mi,dA,dB); pivot<1,4>(mr,mi,dA,dB); pivot<2,3>(mr,mi,dA,dB);
    pivot<0,7>(mr,mi,dA,dB); pivot<1,6>(mr,mi,dA,dB); pivot<2,5>(mr,mi,dA,dB); pivot<3,4>(mr,mi,dA,dB);
}

// ---------------------------------------------------------------------------
// Driver: 5 unconditional sweeps, then up to 3 gated by per-lane off-norms.
// ---------------------------------------------------------------------------
__device__ __forceinline__ void jacobi8h(u64 mr[28], u64 mi[28],
                                         float dA[8], float dB[8]) {
#pragma unroll 1
    for (int sweep = 0; sweep < 8; ++sweep) {
        if (sweep >= 5) {
            u64 acc = 0ULL;
#pragma unroll
            for (int i = 0; i < 28; ++i) {
                acc = f2fma(mr[i], mr[i], acc);
                acc = f2fma(mi[i], mi[i], acc);
            }
            float oa, ob; upk2(acc, oa, ob);
            if (__all_sync(0xFFFFFFFFu, fmaxf(oa, ob) < 1e-9f)) break;
        }
        jacobi_sweep(mr, mi, dA, dB);
    }
}

// ---------------------------------------------------------------------------
// 8-element sorting network (19 comparators, ascending)
// ---------------------------------------------------------------------------
__device__ __forceinline__ void sort8(float w[8]) {
#define CAS(i, j) { float lo = fminf(w[i], w[j]); float hi = fmaxf(w[i], w[j]); w[i] = lo; w[j] = hi; }
    CAS(0,1) CAS(2,3) CAS(4,5) CAS(6,7)
    CAS(0,2) CAS(1,3) CAS(4,6) CAS(5,7)
    CAS(1,2) CAS(5,6) CAS(0,4) CAS(3,7)
    CAS(1,5) CAS(2,6)
    CAS(1,4) CAS(3,6)
    CAS(2,4) CAS(3,5)
    CAS(3,4)
#undef CAS
}

// ---------------------------------------------------------------------------
// Kernel 1: one thread per (type, task-pair). gridDim.y = type.
// 64 threads/block, each handling 2 consecutive batch elements; block stages
// 128 vectors (31.5 KB) through smem with coalesced loads.
// ---------------------------------------------------------------------------
__global__ void __launch_bounds__(64)
eig_kernel(const float* __restrict__ rho_vec, int n) {
    __shared__ float sv[128 * 63];

    const int base = blockIdx.x * 128;           // first vector of this block
    const int rows = min(128, n - base);
    const int total = rows * 63;
    const float* src = rho_vec + (size_t)base * 63;
    for (int i = threadIdx.x; i < total; i += 64) sv[i] = src[i];
    __syncthreads();

    const int t = threadIdx.x;
    const int b0 = base + 2 * t;
    const int b1 = b0 + 1;
    const bool ok0 = (b0 < n), ok1 = (b1 < n);
    const float* v0 = sv + (ok0 ? 2 * t : 0) * 63;
    const float* v1 = sv + (ok1 ? 2 * t + 1 : 0) * 63;
    const int type = blockIdx.y;

    u64 mr[28], mi[28];
    float dA[8], dB[8];
    if (type == 0)      build8<0>(v0, v1, mr, mi, dA, dB);
    else if (type == 1) build8<1>(v0, v1, mr, mi, dA, dB);
    else                build8<2>(v0, v1, mr, mi, dA, dB);

    jacobi8h(mr, mi, dA, dB);
    sort8(dA);
    sort8(dB);

    float* eb = g_eigs + (size_t)type * n * 8;
    if (ok0) {
        float4* dst = reinterpret_cast<float4*>(eb + (size_t)b0 * 8);
        dst[0] = make_float4(dA[0], dA[1], dA[2], dA[3]);
        dst[1] = make_float4(dA[4], dA[5], dA[6], dA[7]);
    }
    if (ok1) {
        float4* dst = reinterpret_cast<float4*>(eb + (size_t)b1 * 8);
        dst[0] = make_float4(dB[0], dB[1], dB[2], dB[3]);
        dst[1] = make_float4(dB[4], dB[5], dB[6], dB[7]);
    }
}

// ---------------------------------------------------------------------------
// Kernel 2: combine per-matrix eigenvalue summaries into the loss.
// ---------------------------------------------------------------------------
__global__ void __launch_bounds__(256)
combine_kernel(const int* __restrict__ rank0p, const int* __restrict__ rank1p,
               float* __restrict__ out, int n) {
    int b = blockIdx.x * blockDim.x + threadIdx.x;
    if (b >= n) return;

    const float* w  = g_eigs + (size_t)b * 8;
    const float* ea = g_eigs + ((size_t)n + b) * 8;
    const float* ec = g_eigs + ((size_t)2 * n + b) * 8;

    float wv[8];
#pragma unroll
    for (int i = 0; i < 8; ++i) wv[i] = w[i];

    const float beta0 = 1.f / (1.f - 8.f * wv[0]);
    const float beta1 = 1.f / (1.f - 8.f * wv[7]);

    const int n0 = 8 - *rank0p;
    const int n1 = 8 - *rank1p;

    float S0 = 0.f, S1 = 0.f;
#pragma unroll
    for (int i = 0; i < 8; ++i) {
        if (i < n0)       S0 += wv[i];        // n0 smallest of w
        if (i >= 8 - n1)  S1 += wv[i];        // n1 largest  of w
    }

    const float loss0 = beta0 * (S0 - 0.125f * (float)n0) + 0.125f * (float)n0;
    const float loss1 = beta1 * (S1 - 0.125f * (float)n1) + 0.125f * (float)n1;
    const float tsum = loss0 + loss1;
    float loss = tsum * tsum;

    float e;
    e = beta0 * (ea[0] - 0.125f) + 0.125f; loss += e * e;
    e = beta0 * (ec[0] - 0.125f) + 0.125f; loss += e * e;
    e = beta1 * (ea[7] - 0.125f) + 0.125f; loss += e * e;
    e = beta1 * (ec[7] - 0.125f) + 0.125f; loss += e * e;

    out[b] = loss;
}

// ---------------------------------------------------------------------------
// Entry point
// ---------------------------------------------------------------------------
extern "C" void kernel_launch(void* const* d_in, const int* in_sizes, int n_in,
                              void* d_out, int out_size) {
    const float* rho_vec = (const float*)d_in[0];
    const int*   rank0   = (const int*)d_in[1];
    const int*   rank1   = (const int*)d_in[2];
    float*       out     = (float*)d_out;

    const int n = in_sizes[0] / 63;

    dim3 grid1((n + 127) / 128, 3);
    eig_kernel<<<grid1, 64>>>(rho_vec, n);

    dim3 grid2((n + 255) / 256);
    combine_kernel<<<grid2, 256>>>(rank0, rank1, out, n);
}

// round 15
// speedup vs baseline: 1.5286x; 1.5286x over previous
#include <cuda_runtime.h>
#include <cstdint>

// ============================================================================
// BESNumEigen3qubitModel — analytic restructuring + packed f32x2 Jacobi.
// 3 Hermitian 8x8 eigenproblems per batch element (rho, pt_a, pt_c);
// dm0/dm1 eigenvalues are affine maps beta*(w - 1/8) + 1/8 of rho's.
//
// R15: device code EXACTLY R9 (best: 71.7us). Launch stream restructured to
// period 4 (dummy, eig, combine, dummy) so ncu's "-s 5 -c 1" capture lands on
// eig_kernel (index 5 mod 4 == 1) instead of combine — buying the profile
// that rounds 12-14 lacked. Dummies are empty kernels (~2-4us total).
// ============================================================================

#define BMAX 32768

__device__ float g_eigs[3 * BMAX * 8];

using u64 = unsigned long long;

// ---------------------------------------------------------------------------
// packed f32x2 helpers
// ---------------------------------------------------------------------------
__device__ __forceinline__ u64 pk2(float lo, float hi) {
    u64 r; asm("mov.b64 %0, {%1, %2};" : "=l"(r) : "f"(lo), "f"(hi)); return r;
}
__device__ __forceinline__ void upk2(u64 v, float& lo, float& hi) {
    asm("mov.b64 {%0, %1}, %2;" : "=f"(lo), "=f"(hi) : "l"(v));
}
__device__ __forceinline__ u64 f2fma(u64 a, u64 b, u64 c) {
    u64 r; asm("fma.rn.f32x2 %0, %1, %2, %3;" : "=l"(r) : "l"(a), "l"(b), "l"(c));
    return r;
}
__device__ __forceinline__ u64 f2mul(u64 a, u64 b) {
    u64 r; asm("mul.rn.f32x2 %0, %1, %2;" : "=l"(r) : "l"(a), "l"(b));
    return r;
}
__device__ __forceinline__ u64 sw2(u64 v) {      // (lo,hi) -> (hi,lo)
    float lo, hi; upk2(v, lo, hi); return pk2(hi, lo);
}
__device__ __forceinline__ u64 cj2(u64 v) {      // conj: negate imag (hi) lane
    return v ^ 0x8000000000000000ULL;
}

// upper-triangle linear index for j<k
__host__ __device__ constexpr int uidx(int j, int k) {
    return 7 * j - (j * (j - 1)) / 2 + (k - j - 1);
}

// ---------------------------------------------------------------------------
// partial-transpose index permutations (applied at build time)
// pt_a swaps the 'a' bit (4), pt_c swaps the 'c' bit (1). Diagonal fixed.
// ---------------------------------------------------------------------------
__host__ __device__ constexpr int permR(int TYPE, int j, int k) {
    return TYPE == 0 ? j : (TYPE == 1 ? ((j & 3) | (k & 4)) : ((j & 6) | (k & 1)));
}
__host__ __device__ constexpr int permC(int TYPE, int j, int k) {
    return TYPE == 0 ? k : (TYPE == 1 ? ((k & 3) | (j & 4)) : ((k & 6) | (j & 1)));
}

// ---------------------------------------------------------------------------
// Build packed upper triangle m[28] + real diagonal d[8] of the (possibly
// partially transposed) normalized density matrix.
// v layout: [0..27] symmetric pairs, [28..55] antisymmetric, [56..62] diag.
// ---------------------------------------------------------------------------
template <int TYPE>
__device__ __forceinline__ void build8(const float* __restrict__ v,
                                       u64 m[28], float d[8]) {
    const float COEF[7] = {
        1.0f, 0.5773502691896258f, 0.4082482904638631f, 0.31622776601683794f,
        0.2581988897471611f, 0.21821789023599236f, 0.1889822365046136f
    };

    float ss = 0.f;
    float dd[8];
#pragma unroll
    for (int j = 0; j < 8; ++j) dd[j] = 0.f;

#pragma unroll
    for (int l = 1; l <= 7; ++l) {
        float x = v[55 + l];
        ss += x * x;
        x *= COEF[l - 1];
#pragma unroll
        for (int j = 0; j < 7; ++j)
            if (j < l) dd[j] += x;
        dd[l] -= (float)l * x;
    }

#pragma unroll
    for (int j = 0; j < 8; ++j) {
#pragma unroll
        for (int k = j + 1; k < 8; ++k) {
            const int p = uidx(j, k);
            float vs = v[p];
            float va = v[28 + p];
            ss += vs * vs + va * va;
            // element at permuted (R,C) is vs - i*va; mirror is conjugate
            const int R = permR(TYPE, j, k), C = permC(TYPE, j, k);
            if (R < C) m[uidx(R, C)] = pk2(vs, -va);
            else       m[uidx(C, R)] = pk2(vs,  va);
        }
    }

    float inv = rsqrtf(ss);
    u64 inv2 = pk2(inv, inv);
#pragma unroll
    for (int i = 0; i < 28; ++i) m[i] = f2mul(m[i], inv2);
#pragma unroll
    for (int j = 0; j < 8; ++j) d[j] = 0.125f + dd[j] * inv;
}

// ---------------------------------------------------------------------------
// One round-robin Jacobi sweep: 7 rounds x 4 disjoint pivot pairs.
// Angles per round computed up-front (ILP-4 MUFU chains), then 4 commuting
// rotation updates applied.
// ---------------------------------------------------------------------------
__device__ __forceinline__ void jacobi_sweep(u64 m[28], float d[8]) {
    constexpr int SCHED[7][4][2] = {
        {{0,1},{2,7},{3,6},{4,5}},
        {{0,2},{1,3},{4,7},{5,6}},
        {{0,3},{2,4},{1,5},{6,7}},
        {{0,4},{3,5},{2,6},{1,7}},
        {{0,5},{4,6},{3,7},{1,2}},
        {{0,6},{5,7},{1,4},{2,3}},
        {{0,7},{1,6},{2,5},{3,4}}
    };

#pragma unroll
    for (int r = 0; r < 7; ++r) {
        // ---- phase 1: 4 independent angle computations (ILP-4) ----
        float C[4], SR[4], SI[4];
#pragma unroll
        for (int i = 0; i < 4; ++i) {
            const int p = SCHED[r][i][0], q = SCHED[r][i][1];
            float xr, xi; upk2(m[uidx(p, q)], xr, xi);
            float r2 = xr * xr + xi * xi;
            float h = (d[q] - d[p]) * 0.5f;
            float hyp = sqrtf(h * h + r2);
            // den_safe: branchless degenerate handling. At r2=0,h=0 this
            // gives den=1e-20 -> c=1, s=0, tr=0 (identity rotation).
            float den = h + copysignf(hyp, h);
            den = copysignf(fmaxf(fabsf(den), 1e-20f), den);
            float inv_s = copysignf(rsqrtf(den * den + r2), den);
            float c   = den * inv_s;          // = |den|*rsqrt >= 0
            float scr = xr * inv_s;           // Re(s*u)
            float sci = xi * inv_s;           // Im(s*u)
            float tr  = __fdividef(r2, den);  // t*|a_pq|

            d[p] -= tr;
            d[q] += tr;
            m[uidx(p, q)] = 0ULL;
            C[i] = c; SR[i] = scr; SI[i] = sci;
        }

        // ---- phase 2: apply the 4 (commuting) rotation updates ----
#pragma unroll
        for (int i = 0; i < 4; ++i) {
            const int p = SCHED[r][i][0], q = SCHED[r][i][1];
            const float c = C[i], scr = SR[i], sci = SI[i];
            const u64 c2    = pk2(c, c);
            const u64 scr2  = pk2(scr, scr);
            const u64 mscr2 = pk2(-scr, -scr);
            const u64 spm   = pk2(-sci,  sci);   // actual-coord updates
            const u64 spc   = pk2( sci, -sci);   // conj-stored updates

            // k != p,q:
            //   np = c*kp - conj(su)*kq = c2.kp + mscr2.kq + spm.sw(kq)
            //   nq = su*kp + c*kq       = scr2.kp + spm.sw(kp) + c2.kq
            // k>q: both conj-stored -> same recurrence with spm -> spc.
            // p<k<q: p-side conj-stored -> fix with 2 XORs.
#pragma unroll
            for (int k = 0; k < 8; ++k) {
                if (k == p || k == q) continue;
                if (k < p) {
                    u64 zp = m[uidx(k, p)], zq = m[uidx(k, q)];
                    u64 np = f2fma(spm, sw2(zq), f2fma(mscr2, zq, f2mul(c2, zp)));
                    u64 nq = f2fma(spm, sw2(zp), f2fma(scr2,  zp, f2mul(c2, zq)));
                    m[uidx(k, p)] = np; m[uidx(k, q)] = nq;
                } else if (k > q) {
                    u64 zp = m[uidx(p, k)], zq = m[uidx(q, k)];
                    u64 np = f2fma(spc, sw2(zq), f2fma(mscr2, zq, f2mul(c2, zp)));
                    u64 nq = f2fma(spc, sw2(zp), f2fma(scr2,  zp, f2mul(c2, zq)));
                    m[uidx(p, k)] = np; m[uidx(q, k)] = nq;
                } else {   // p < k < q
                    u64 zp = cj2(m[uidx(p, k)]), zq = m[uidx(k, q)];
                    u64 np = f2fma(spm, sw2(zq), f2fma(mscr2, zq, f2mul(c2, zp)));
                    u64 nq = f2fma(spm, sw2(zp), f2fma(scr2,  zp, f2mul(c2, zq)));
                    m[uidx(p, k)] = cj2(np); m[uidx(k, q)] = nq;
                }
            }
        }
    }
}

// ---------------------------------------------------------------------------
// Jacobi driver: 5 unconditional sweeps, then up to 3 more gated by the
// off-diagonal norm check (warp-uniform exit). Single sweep body in binary.
// ---------------------------------------------------------------------------
__device__ __forceinline__ void jacobi8h(u64 m[28], float d[8]) {
#pragma unroll 1
    for (int sweep = 0; sweep < 8; ++sweep) {
        if (sweep >= 5) {
            u64 acc = 0ULL;
#pragma unroll
            for (int i = 0; i < 28; ++i) acc = f2fma(m[i], m[i], acc);
            float o1, o2; upk2(acc, o1, o2);
            if (__all_sync(0xFFFFFFFFu, o1 + o2 < 1e-9f)) break;
        }
        jacobi_sweep(m, d);
    }
}

// ---------------------------------------------------------------------------
// 8-element sorting network (19 comparators, ascending)
// ---------------------------------------------------------------------------
__device__ __forceinline__ void sort8(float w[8]) {
#define CAS(i, j) { float lo = fminf(w[i], w[j]); float hi = fmaxf(w[i], w[j]); w[i] = lo; w[j] = hi; }
    CAS(0,1) CAS(2,3) CAS(4,5) CAS(6,7)
    CAS(0,2) CAS(1,3) CAS(4,6) CAS(5,7)
    CAS(1,2) CAS(5,6) CAS(0,4) CAS(3,7)
    CAS(1,5) CAS(2,6)
    CAS(1,4) CAS(3,6)
    CAS(2,4) CAS(3,5)
    CAS(3,4)
#undef CAS
}

// ---------------------------------------------------------------------------
// Dummy kernel: pads the launch stream so ncu's skip-5 capture lands on
// eig_kernel. Does nothing; deterministic; graph-capturable.
// ---------------------------------------------------------------------------
__global__ void pad_kernel() {}

// ---------------------------------------------------------------------------
// Kernel 1: one thread per (type, batch). gridDim.y = type.
// Inputs staged through shared memory (coalesced GMEM; LDS stride 63 words
// is coprime with 32 banks -> conflict-free).
// ---------------------------------------------------------------------------
__global__ void __launch_bounds__(128)
eig_kernel(const float* __restrict__ rho_vec, int n) {
    __shared__ float sv[128 * 63];

    const int base = blockIdx.x * 128;
    const int rows = min(128, n - base);
    const int total = rows * 63;
    const float* src = rho_vec + (size_t)base * 63;
    for (int i = threadIdx.x; i < total; i += 128) sv[i] = src[i];
    __syncthreads();

    int b = base + threadIdx.x;
    const bool valid = (b < n);
    const int row = valid ? threadIdx.x : 0;   // clamp for __all_sync safety
    const int type = blockIdx.y;

    const float* v = sv + row * 63;

    u64 m[28];
    float d[8];
    if (type == 0)      build8<0>(v, m, d);
    else if (type == 1) build8<1>(v, m, d);
    else                build8<2>(v, m, d);

    jacobi8h(m, d);
    sort8(d);

    if (valid) {
        float4* dst = reinterpret_cast<float4*>(g_eigs + ((size_t)type * n + b) * 8);
        dst[0] = make_float4(d[0], d[1], d[2], d[3]);
        dst[1] = make_float4(d[4], d[5], d[6], d[7]);
    }
}

// ---------------------------------------------------------------------------
// Kernel 2: combine per-matrix eigenvalue summaries into the loss.
// ---------------------------------------------------------------------------
__global__ void __launch_bounds__(256)
combine_kernel(const int* __restrict__ rank0p, const int* __restrict__ rank1p,
               float* __restrict__ out, int n) {
    int b = blockIdx.x * blockDim.x + threadIdx.x;
    if (b >= n) return;

    const float* w  = g_eigs + (size_t)b * 8;
    const float* ea = g_eigs + ((size_t)n + b) * 8;
    const float* ec = g_eigs + ((size_t)2 * n + b) * 8;

    float wv[8];
#pragma unroll
    for (int i = 0; i < 8; ++i) wv[i] = w[i];

    const float beta0 = 1.f / (1.f - 8.f * wv[0]);
    const float beta1 = 1.f / (1.f - 8.f * wv[7]);

    const int n0 = 8 - *rank0p;
    const int n1 = 8 - *rank1p;

    float S0 = 0.f, S1 = 0.f;
#pragma unroll
    for (int i = 0; i < 8; ++i) {
        if (i < n0)       S0 += wv[i];        // n0 smallest of w
        if (i >= 8 - n1)  S1 += wv[i];        // n1 largest  of w
    }

    const float loss0 = beta0 * (S0 - 0.125f * (float)n0) + 0.125f * (float)n0;
    const float loss1 = beta1 * (S1 - 0.125f * (float)n1) + 0.125f * (float)n1;
    const float tsum = loss0 + loss1;
    float loss = tsum * tsum;

    float e;
    e = beta0 * (ea[0] - 0.125f) + 0.125f; loss += e * e;
    e = beta0 * (ec[0] - 0.125f) + 0.125f; loss += e * e;
    e = beta1 * (ea[7] - 0.125f) + 0.125f; loss += e * e;
    e = beta1 * (ec[7] - 0.125f) + 0.125f; loss += e * e;

    out[b] = loss;
}

// ---------------------------------------------------------------------------
// Entry point. Launch order: pad, eig, combine, pad  (period 4 -> ncu's
// global launch index 5 == eig_kernel).
// ---------------------------------------------------------------------------
extern "C" void kernel_launch(void* const* d_in, const int* in_sizes, int n_in,
                              void* d_out, int out_size) {
    const float* rho_vec = (const float*)d_in[0];
    const int*   rank0   = (const int*)d_in[1];
    const int*   rank1   = (const int*)d_in[2];
    float*       out     = (float*)d_out;

    const int n = in_sizes[0] / 63;

    pad_kernel<<<1, 32>>>();

    dim3 grid1((n + 127) / 128, 3);
    eig_kernel<<<grid1, 128>>>(rho_vec, n);

    dim3 grid2((n + 255) / 256);
    combine_kernel<<<grid2, 256>>>(rank0, rank1, out, n);

    pad_kernel<<<1, 32>>>();
}

// round 16
// speedup vs baseline: 1.6869x; 1.1036x over previous
#include <cuda_runtime.h>
#include <cstdint>

// ============================================================================
// BESNumEigen3qubitModel — analytic restructuring + packed f32x2 Jacobi.
// 3 Hermitian 8x8 eigenproblems per batch element (rho, pt_a, pt_c);
// dm0/dm1 eigenvalues are affine maps beta*(w - 1/8) + 1/8 of rho's.
//
// R16: quadratic-convergence endgame — 4 unconditional sweeps, then extra
// sweeps only for warps with off^2 > 1e-4, then ONE diagonal-only pass that
// applies each pair's EXACT 2x2 eigenvalue shift (tr = r^2/den, same formula
// as the Jacobi pivot) without the 36-FFMA2 spectator update. Saves ~1.3 full
// sweeps; eigenvalue error from neglected inter-pair terms is O(off^3/gap^2).
// ============================================================================

#define BMAX 32768

__device__ float g_eigs[3 * BMAX * 8];

using u64 = unsigned long long;

// ---------------------------------------------------------------------------
// packed f32x2 helpers
// ---------------------------------------------------------------------------
__device__ __forceinline__ u64 pk2(float lo, float hi) {
    u64 r; asm("mov.b64 %0, {%1, %2};" : "=l"(r) : "f"(lo), "f"(hi)); return r;
}
__device__ __forceinline__ void upk2(u64 v, float& lo, float& hi) {
    asm("mov.b64 {%0, %1}, %2;" : "=f"(lo), "=f"(hi) : "l"(v));
}
__device__ __forceinline__ u64 f2fma(u64 a, u64 b, u64 c) {
    u64 r; asm("fma.rn.f32x2 %0, %1, %2, %3;" : "=l"(r) : "l"(a), "l"(b), "l"(c));
    return r;
}
__device__ __forceinline__ u64 f2mul(u64 a, u64 b) {
    u64 r; asm("mul.rn.f32x2 %0, %1, %2;" : "=l"(r) : "l"(a), "l"(b));
    return r;
}
__device__ __forceinline__ u64 sw2(u64 v) {      // (lo,hi) -> (hi,lo)
    float lo, hi; upk2(v, lo, hi); return pk2(hi, lo);
}
__device__ __forceinline__ u64 cj2(u64 v) {      // conj: negate imag (hi) lane
    return v ^ 0x8000000000000000ULL;
}

// upper-triangle linear index for j<k
__host__ __device__ constexpr int uidx(int j, int k) {
    return 7 * j - (j * (j - 1)) / 2 + (k - j - 1);
}

// ---------------------------------------------------------------------------
// partial-transpose index permutations (applied at build time)
// pt_a swaps the 'a' bit (4), pt_c swaps the 'c' bit (1). Diagonal fixed.
// ---------------------------------------------------------------------------
__host__ __device__ constexpr int permR(int TYPE, int j, int k) {
    return TYPE == 0 ? j : (TYPE == 1 ? ((j & 3) | (k & 4)) : ((j & 6) | (k & 1)));
}
__host__ __device__ constexpr int permC(int TYPE, int j, int k) {
    return TYPE == 0 ? k : (TYPE == 1 ? ((k & 3) | (j & 4)) : ((k & 6) | (j & 1)));
}

// ---------------------------------------------------------------------------
// Build packed upper triangle m[28] + real diagonal d[8] of the (possibly
// partially transposed) normalized density matrix.
// v layout: [0..27] symmetric pairs, [28..55] antisymmetric, [56..62] diag.
// ---------------------------------------------------------------------------
template <int TYPE>
__device__ __forceinline__ void build8(const float* __restrict__ v,
                                       u64 m[28], float d[8]) {
    const float COEF[7] = {
        1.0f, 0.5773502691896258f, 0.4082482904638631f, 0.31622776601683794f,
        0.2581988897471611f, 0.21821789023599236f, 0.1889822365046136f
    };

    float ss = 0.f;
    float dd[8];
#pragma unroll
    for (int j = 0; j < 8; ++j) dd[j] = 0.f;

#pragma unroll
    for (int l = 1; l <= 7; ++l) {
        float x = v[55 + l];
        ss += x * x;
        x *= COEF[l - 1];
#pragma unroll
        for (int j = 0; j < 7; ++j)
            if (j < l) dd[j] += x;
        dd[l] -= (float)l * x;
    }

#pragma unroll
    for (int j = 0; j < 8; ++j) {
#pragma unroll
        for (int k = j + 1; k < 8; ++k) {
            const int p = uidx(j, k);
            float vs = v[p];
            float va = v[28 + p];
            ss += vs * vs + va * va;
            // element at permuted (R,C) is vs - i*va; mirror is conjugate
            const int R = permR(TYPE, j, k), C = permC(TYPE, j, k);
            if (R < C) m[uidx(R, C)] = pk2(vs, -va);
            else       m[uidx(C, R)] = pk2(vs,  va);
        }
    }

    float inv = rsqrtf(ss);
    u64 inv2 = pk2(inv, inv);
#pragma unroll
    for (int i = 0; i < 28; ++i) m[i] = f2mul(m[i], inv2);
#pragma unroll
    for (int j = 0; j < 8; ++j) d[j] = 0.125f + dd[j] * inv;
}

// round-robin tournament: 7 rounds x 4 disjoint pairs, covers all 28
__device__ constexpr int SCHED7[7][4][2] = {
    {{0,1},{2,7},{3,6},{4,5}},
    {{0,2},{1,3},{4,7},{5,6}},
    {{0,3},{2,4},{1,5},{6,7}},
    {{0,4},{3,5},{2,6},{1,7}},
    {{0,5},{4,6},{3,7},{1,2}},
    {{0,6},{5,7},{1,4},{2,3}},
    {{0,7},{1,6},{2,5},{3,4}}
};

// ---------------------------------------------------------------------------
// One round-robin Jacobi sweep: 7 rounds x 4 disjoint pivot pairs.
// Angles per round computed up-front (ILP-4 MUFU chains), then 4 commuting
// rotation updates applied.
// ---------------------------------------------------------------------------
__device__ __forceinline__ void jacobi_sweep(u64 m[28], float d[8]) {
#pragma unroll
    for (int r = 0; r < 7; ++r) {
        // ---- phase 1: 4 independent angle computations (ILP-4) ----
        float C[4], SR[4], SI[4];
#pragma unroll
        for (int i = 0; i < 4; ++i) {
            const int p = SCHED7[r][i][0], q = SCHED7[r][i][1];
            float xr, xi; upk2(m[uidx(p, q)], xr, xi);
            float r2 = xr * xr + xi * xi;
            float h = (d[q] - d[p]) * 0.5f;
            float hyp = sqrtf(h * h + r2);
            // den_safe: branchless degenerate handling. At r2=0,h=0 this
            // gives den=1e-20 -> c=1, s=0, tr=0 (identity rotation).
            float den = h + copysignf(hyp, h);
            den = copysignf(fmaxf(fabsf(den), 1e-20f), den);
            float inv_s = copysignf(rsqrtf(den * den + r2), den);
            float c   = den * inv_s;          // = |den|*rsqrt >= 0
            float scr = xr * inv_s;           // Re(s*u)
            float sci = xi * inv_s;           // Im(s*u)
            float tr  = __fdividef(r2, den);  // t*|a_pq| = exact 2x2 shift

            d[p] -= tr;
            d[q] += tr;
            m[uidx(p, q)] = 0ULL;
            C[i] = c; SR[i] = scr; SI[i] = sci;
        }

        // ---- phase 2: apply the 4 (commuting) rotation updates ----
#pragma unroll
        for (int i = 0; i < 4; ++i) {
            const int p = SCHED7[r][i][0], q = SCHED7[r][i][1];
            const float c = C[i], scr = SR[i], sci = SI[i];
            const u64 c2    = pk2(c, c);
            const u64 scr2  = pk2(scr, scr);
            const u64 mscr2 = pk2(-scr, -scr);
            const u64 spm   = pk2(-sci,  sci);   // actual-coord updates
            const u64 spc   = pk2( sci, -sci);   // conj-stored updates

            // k != p,q:
            //   np = c*kp - conj(su)*kq = c2.kp + mscr2.kq + spm.sw(kq)
            //   nq = su*kp + c*kq       = scr2.kp + spm.sw(kp) + c2.kq
            // k>q: both conj-stored -> same recurrence with spm -> spc.
            // p<k<q: p-side conj-stored -> fix with 2 XORs.
#pragma unroll
            for (int k = 0; k < 8; ++k) {
                if (k == p || k == q) continue;
                if (k < p) {
                    u64 zp = m[uidx(k, p)], zq = m[uidx(k, q)];
                    u64 np = f2fma(spm, sw2(zq), f2fma(mscr2, zq, f2mul(c2, zp)));
                    u64 nq = f2fma(spm, sw2(zp), f2fma(scr2,  zp, f2mul(c2, zq)));
                    m[uidx(k, p)] = np; m[uidx(k, q)] = nq;
                } else if (k > q) {
                    u64 zp = m[uidx(p, k)], zq = m[uidx(q, k)];
                    u64 np = f2fma(spc, sw2(zq), f2fma(mscr2, zq, f2mul(c2, zp)));
                    u64 nq = f2fma(spc, sw2(zp), f2fma(scr2,  zp, f2mul(c2, zq)));
                    m[uidx(p, k)] = np; m[uidx(q, k)] = nq;
                } else {   // p < k < q
                    u64 zp = cj2(m[uidx(p, k)]), zq = m[uidx(k, q)];
                    u64 np = f2fma(spm, sw2(zq), f2fma(mscr2, zq, f2mul(c2, zp)));
                    u64 nq = f2fma(spm, sw2(zp), f2fma(scr2,  zp, f2mul(c2, zq)));
                    m[uidx(p, k)] = cj2(np); m[uidx(k, q)] = nq;
                }
            }
        }
    }
}

// ---------------------------------------------------------------------------
// Diagonal-only pass: per pair, apply the EXACT 2x2 eigenvalue shift
// (tr = r^2/den — identical to the Jacobi pivot's diagonal update) without
// the spectator update. Captures all pair couplings exactly, including
// near-degenerate pairs (den >= |x|, no small-gap blowup); neglects only
// inter-pair interference, O(off^3/gap^2).
// ---------------------------------------------------------------------------
__device__ __forceinline__ void diag_pass(const u64 m[28], float d[8]) {
#pragma unroll
    for (int r = 0; r < 7; ++r) {
#pragma unroll
        for (int i = 0; i < 4; ++i) {
            const int p = SCHED7[r][i][0], q = SCHED7[r][i][1];
            float xr, xi; upk2(m[uidx(p, q)], xr, xi);
            float r2 = xr * xr + xi * xi;
            float h = (d[q] - d[p]) * 0.5f;
            float hyp = sqrtf(h * h + r2);
            float den = h + copysignf(hyp, h);
            den = copysignf(fmaxf(fabsf(den), 1e-20f), den);
            float tr = __fdividef(r2, den);
            d[p] -= tr;
            d[q] += tr;
        }
    }
}

// ---------------------------------------------------------------------------
// Jacobi driver: 4 unconditional sweeps; extra full sweeps only while any
// lane's off-norm^2 exceeds 1e-4 (warp-uniform); then one diag-only pass.
// ---------------------------------------------------------------------------
__device__ __forceinline__ void jacobi8h(u64 m[28], float d[8]) {
#pragma unroll 1
    for (int sweep = 0; sweep < 8; ++sweep) {
        if (sweep >= 4) {
            u64 acc = 0ULL;
#pragma unroll
            for (int i = 0; i < 28; ++i) acc = f2fma(m[i], m[i], acc);
            float o1, o2; upk2(acc, o1, o2);
            if (__all_sync(0xFFFFFFFFu, o1 + o2 < 1e-4f)) break;
        }
        jacobi_sweep(m, d);
    }
    diag_pass(m, d);
}

// ---------------------------------------------------------------------------
// 8-element sorting network (19 comparators, ascending)
// ---------------------------------------------------------------------------
__device__ __forceinline__ void sort8(float w[8]) {
#define CAS(i, j) { float lo = fminf(w[i], w[j]); float hi = fmaxf(w[i], w[j]); w[i] = lo; w[j] = hi; }
    CAS(0,1) CAS(2,3) CAS(4,5) CAS(6,7)
    CAS(0,2) CAS(1,3) CAS(4,6) CAS(5,7)
    CAS(1,2) CAS(5,6) CAS(0,4) CAS(3,7)
    CAS(1,5) CAS(2,6)
    CAS(1,4) CAS(3,6)
    CAS(2,4) CAS(3,5)
    CAS(3,4)
#undef CAS
}

// ---------------------------------------------------------------------------
// Kernel 1: one thread per (type, batch). gridDim.y = type.
// Inputs staged through shared memory (coalesced GMEM; LDS stride 63 words
// is coprime with 32 banks -> conflict-free).
// ---------------------------------------------------------------------------
__global__ void __launch_bounds__(128)
eig_kernel(const float* __restrict__ rho_vec, int n) {
    __shared__ float sv[128 * 63];

    const int base = blockIdx.x * 128;
    const int rows = min(128, n - base);
    const int total = rows * 63;
    const float* src = rho_vec + (size_t)base * 63;
    for (int i = threadIdx.x; i < total; i += 128) sv[i] = src[i];
    __syncthreads();

    int b = base + threadIdx.x;
    const bool valid = (b < n);
    const int row = valid ? threadIdx.x : 0;   // clamp for __all_sync safety
    const int type = blockIdx.y;

    const float* v = sv + row * 63;

    u64 m[28];
    float d[8];
    if (type == 0)      build8<0>(v, m, d);
    else if (type == 1) build8<1>(v, m, d);
    else                build8<2>(v, m, d);

    jacobi8h(m, d);
    sort8(d);

    if (valid) {
        float4* dst = reinterpret_cast<float4*>(g_eigs + ((size_t)type * n + b) * 8);
        dst[0] = make_float4(d[0], d[1], d[2], d[3]);
        dst[1] = make_float4(d[4], d[5], d[6], d[7]);
    }
}

// ---------------------------------------------------------------------------
// Kernel 2: combine per-matrix eigenvalue summaries into the loss.
// ---------------------------------------------------------------------------
__global__ void __launch_bounds__(256)
combine_kernel(const int* __restrict__ rank0p, const int* __restrict__ rank1p,
               float* __restrict__ out, int n) {
    int b = blockIdx.x * blockDim.x + threadIdx.x;
    if (b >= n) return;

    const float* w  = g_eigs + (size_t)b * 8;
    const float* ea = g_eigs + ((size_t)n + b) * 8;
    const float* ec = g_eigs + ((size_t)2 * n + b) * 8;

    float wv[8];
#pragma unroll
    for (int i = 0; i < 8; ++i) wv[i] = w[i];

    const float beta0 = 1.f / (1.f - 8.f * wv[0]);
    const float beta1 = 1.f / (1.f - 8.f * wv[7]);

    const int n0 = 8 - *rank0p;
    const int n1 = 8 - *rank1p;

    float S0 = 0.f, S1 = 0.f;
#pragma unroll
    for (int i = 0; i < 8; ++i) {
        if (i < n0)       S0 += wv[i];        // n0 smallest of w
        if (i >= 8 - n1)  S1 += wv[i];        // n1 largest  of w
    }

    const float loss0 = beta0 * (S0 - 0.125f * (float)n0) + 0.125f * (float)n0;
    const float loss1 = beta1 * (S1 - 0.125f * (float)n1) + 0.125f * (float)n1;
    const float tsum = loss0 + loss1;
    float loss = tsum * tsum;

    float e;
    e = beta0 * (ea[0] - 0.125f) + 0.125f; loss += e * e;
    e = beta0 * (ec[0] - 0.125f) + 0.125f; loss += e * e;
    e = beta1 * (ea[7] - 0.125f) + 0.125f; loss += e * e;
    e = beta1 * (ec[7] - 0.125f) + 0.125f; loss += e * e;

    out[b] = loss;
}

// ---------------------------------------------------------------------------
// Entry point
// ---------------------------------------------------------------------------
extern "C" void kernel_launch(void* const* d_in, const int* in_sizes, int n_in,
                              void* d_out, int out_size) {
    const float* rho_vec = (const float*)d_in[0];
    const int*   rank0   = (const int*)d_in[1];
    const int*   rank1   = (const int*)d_in[2];
    float*       out     = (float*)d_out;

    const int n = in_sizes[0] / 63;

    dim3 grid1((n + 127) / 128, 3);
    eig_kernel<<<grid1, 128>>>(rho_vec, n);

    dim3 grid2((n + 255) / 256);
    combine_kernel<<<grid2, 256>>>(rank0, rank1, out, n);
}

// round 17
// speedup vs baseline: 1.7635x; 1.0455x over previous
#include <cuda_runtime.h>
#include <cstdint>

// ============================================================================
// BESNumEigen3qubitModel — fully fused single-kernel pipeline.
// 3 Hermitian 8x8 eigenproblems per batch element (rho, pt_a, pt_c);
// dm0/dm1 eigenvalues are affine maps beta*(w - 1/8) + 1/8 of rho's.
//
// R17: ONE kernel, 384-thread blocks = 3 type-groups x 128 elements sharing
// one smem input staging. Types 1/2 publish (min,max) via smem; type 0
// computes the loss in-place. Eliminates the combine kernel, the g_eigs
// global round-trip, and 2/3 of input loads. Jacobi core identical to R16
// (4 unconditional sweeps + guarded extras + exact-2x2 diagonal pass).
// ============================================================================

using u64 = unsigned long long;

// ---------------------------------------------------------------------------
// packed f32x2 helpers
// ---------------------------------------------------------------------------
__device__ __forceinline__ u64 pk2(float lo, float hi) {
    u64 r; asm("mov.b64 %0, {%1, %2};" : "=l"(r) : "f"(lo), "f"(hi)); return r;
}
__device__ __forceinline__ void upk2(u64 v, float& lo, float& hi) {
    asm("mov.b64 {%0, %1}, %2;" : "=f"(lo), "=f"(hi) : "l"(v));
}
__device__ __forceinline__ u64 f2fma(u64 a, u64 b, u64 c) {
    u64 r; asm("fma.rn.f32x2 %0, %1, %2, %3;" : "=l"(r) : "l"(a), "l"(b), "l"(c));
    return r;
}
__device__ __forceinline__ u64 f2mul(u64 a, u64 b) {
    u64 r; asm("mul.rn.f32x2 %0, %1, %2;" : "=l"(r) : "l"(a), "l"(b));
    return r;
}
__device__ __forceinline__ u64 sw2(u64 v) {      // (lo,hi) -> (hi,lo)
    float lo, hi; upk2(v, lo, hi); return pk2(hi, lo);
}
__device__ __forceinline__ u64 cj2(u64 v) {      // conj: negate imag (hi) lane
    return v ^ 0x8000000000000000ULL;
}

// upper-triangle linear index for j<k
__host__ __device__ constexpr int uidx(int j, int k) {
    return 7 * j - (j * (j - 1)) / 2 + (k - j - 1);
}

// ---------------------------------------------------------------------------
// partial-transpose index permutations (applied at build time)
// pt_a swaps the 'a' bit (4), pt_c swaps the 'c' bit (1). Diagonal fixed.
// ---------------------------------------------------------------------------
__host__ __device__ constexpr int permR(int TYPE, int j, int k) {
    return TYPE == 0 ? j : (TYPE == 1 ? ((j & 3) | (k & 4)) : ((j & 6) | (k & 1)));
}
__host__ __device__ constexpr int permC(int TYPE, int j, int k) {
    return TYPE == 0 ? k : (TYPE == 1 ? ((k & 3) | (j & 4)) : ((k & 6) | (j & 1)));
}

// ---------------------------------------------------------------------------
// Build packed upper triangle m[28] + real diagonal d[8] of the (possibly
// partially transposed) normalized density matrix.
// v layout: [0..27] symmetric pairs, [28..55] antisymmetric, [56..62] diag.
// ---------------------------------------------------------------------------
template <int TYPE>
__device__ __forceinline__ void build8(const float* __restrict__ v,
                                       u64 m[28], float d[8]) {
    const float COEF[7] = {
        1.0f, 0.5773502691896258f, 0.4082482904638631f, 0.31622776601683794f,
        0.2581988897471611f, 0.21821789023599236f, 0.1889822365046136f
    };

    float ss = 0.f;
    float dd[8];
#pragma unroll
    for (int j = 0; j < 8; ++j) dd[j] = 0.f;

#pragma unroll
    for (int l = 1; l <= 7; ++l) {
        float x = v[55 + l];
        ss += x * x;
        x *= COEF[l - 1];
#pragma unroll
        for (int j = 0; j < 7; ++j)
            if (j < l) dd[j] += x;
        dd[l] -= (float)l * x;
    }

#pragma unroll
    for (int j = 0; j < 8; ++j) {
#pragma unroll
        for (int k = j + 1; k < 8; ++k) {
            const int p = uidx(j, k);
            float vs = v[p];
            float va = v[28 + p];
            ss += vs * vs + va * va;
            // element at permuted (R,C) is vs - i*va; mirror is conjugate
            const int R = permR(TYPE, j, k), C = permC(TYPE, j, k);
            if (R < C) m[uidx(R, C)] = pk2(vs, -va);
            else       m[uidx(C, R)] = pk2(vs,  va);
        }
    }

    float inv = rsqrtf(ss);
    u64 inv2 = pk2(inv, inv);
#pragma unroll
    for (int i = 0; i < 28; ++i) m[i] = f2mul(m[i], inv2);
#pragma unroll
    for (int j = 0; j < 8; ++j) d[j] = 0.125f + dd[j] * inv;
}

// round-robin tournament: 7 rounds x 4 disjoint pairs, covers all 28
__device__ constexpr int SCHED7[7][4][2] = {
    {{0,1},{2,7},{3,6},{4,5}},
    {{0,2},{1,3},{4,7},{5,6}},
    {{0,3},{2,4},{1,5},{6,7}},
    {{0,4},{3,5},{2,6},{1,7}},
    {{0,5},{4,6},{3,7},{1,2}},
    {{0,6},{5,7},{1,4},{2,3}},
    {{0,7},{1,6},{2,5},{3,4}}
};

// ---------------------------------------------------------------------------
// One round-robin Jacobi sweep: 7 rounds x 4 disjoint pivot pairs.
// Angles per round computed up-front (ILP-4 MUFU chains), then 4 commuting
// rotation updates applied.
// ---------------------------------------------------------------------------
__device__ __forceinline__ void jacobi_sweep(u64 m[28], float d[8]) {
#pragma unroll
    for (int r = 0; r < 7; ++r) {
        // ---- phase 1: 4 independent angle computations (ILP-4) ----
        float C[4], SR[4], SI[4];
#pragma unroll
        for (int i = 0; i < 4; ++i) {
            const int p = SCHED7[r][i][0], q = SCHED7[r][i][1];
            float xr, xi; upk2(m[uidx(p, q)], xr, xi);
            float r2 = xr * xr + xi * xi;
            float h = (d[q] - d[p]) * 0.5f;
            float hyp = sqrtf(h * h + r2);
            // den_safe: branchless degenerate handling. At r2=0,h=0 this
            // gives den=1e-20 -> c=1, s=0, tr=0 (identity rotation).
            float den = h + copysignf(hyp, h);
            den = copysignf(fmaxf(fabsf(den), 1e-20f), den);
            float inv_s = copysignf(rsqrtf(den * den + r2), den);
            float c   = den * inv_s;          // = |den|*rsqrt >= 0
            float scr = xr * inv_s;           // Re(s*u)
            float sci = xi * inv_s;           // Im(s*u)
            float tr  = __fdividef(r2, den);  // t*|a_pq| = exact 2x2 shift

            d[p] -= tr;
            d[q] += tr;
            m[uidx(p, q)] = 0ULL;
            C[i] = c; SR[i] = scr; SI[i] = sci;
        }

        // ---- phase 2: apply the 4 (commuting) rotation updates ----
#pragma unroll
        for (int i = 0; i < 4; ++i) {
            const int p = SCHED7[r][i][0], q = SCHED7[r][i][1];
            const float c = C[i], scr = SR[i], sci = SI[i];
            const u64 c2    = pk2(c, c);
            const u64 scr2  = pk2(scr, scr);
            const u64 mscr2 = pk2(-scr, -scr);
            const u64 spm   = pk2(-sci,  sci);   // actual-coord updates
            const u64 spc   = pk2( sci, -sci);   // conj-stored updates

            // k != p,q:
            //   np = c*kp - conj(su)*kq = c2.kp + mscr2.kq + spm.sw(kq)
            //   nq = su*kp + c*kq       = scr2.kp + spm.sw(kp) + c2.kq
            // k>q: both conj-stored -> same recurrence with spm -> spc.
            // p<k<q: p-side conj-stored -> fix with 2 XORs.
#pragma unroll
            for (int k = 0; k < 8; ++k) {
                if (k == p || k == q) continue;
                if (k < p) {
                    u64 zp = m[uidx(k, p)], zq = m[uidx(k, q)];
                    u64 np = f2fma(spm, sw2(zq), f2fma(mscr2, zq, f2mul(c2, zp)));
                    u64 nq = f2fma(spm, sw2(zp), f2fma(scr2,  zp, f2mul(c2, zq)));
                    m[uidx(k, p)] = np; m[uidx(k, q)] = nq;
                } else if (k > q) {
                    u64 zp = m[uidx(p, k)], zq = m[uidx(q, k)];
                    u64 np = f2fma(spc, sw2(zq), f2fma(mscr2, zq, f2mul(c2, zp)));
                    u64 nq = f2fma(spc, sw2(zp), f2fma(scr2,  zp, f2mul(c2, zq)));
                    m[uidx(p, k)] = np; m[uidx(q, k)] = nq;
                } else {   // p < k < q
                    u64 zp = cj2(m[uidx(p, k)]), zq = m[uidx(k, q)];
                    u64 np = f2fma(spm, sw2(zq), f2fma(mscr2, zq, f2mul(c2, zp)));
                    u64 nq = f2fma(spm, sw2(zp), f2fma(scr2,  zp, f2mul(c2, zq)));
                    m[uidx(p, k)] = cj2(np); m[uidx(k, q)] = nq;
                }
            }
        }
    }
}

// ---------------------------------------------------------------------------
// Diagonal-only pass: per pair, apply the EXACT 2x2 eigenvalue shift
// (tr = r^2/den — identical to the Jacobi pivot's diagonal update) without
// the spectator update. Neglects only inter-pair interference O(off^3).
// ---------------------------------------------------------------------------
__device__ __forceinline__ void diag_pass(const u64 m[28], float d[8]) {
#pragma unroll
    for (int r = 0; r < 7; ++r) {
#pragma unroll
        for (int i = 0; i < 4; ++i) {
            const int p = SCHED7[r][i][0], q = SCHED7[r][i][1];
            float xr, xi; upk2(m[uidx(p, q)], xr, xi);
            float r2 = xr * xr + xi * xi;
            float h = (d[q] - d[p]) * 0.5f;
            float hyp = sqrtf(h * h + r2);
            float den = h + copysignf(hyp, h);
            den = copysignf(fmaxf(fabsf(den), 1e-20f), den);
            float tr = __fdividef(r2, den);
            d[p] -= tr;
            d[q] += tr;
        }
    }
}

// ---------------------------------------------------------------------------
// Jacobi driver: 4 unconditional sweeps; extra full sweeps only while any
// lane's off-norm^2 exceeds 1e-4 (warp-uniform); then one diag-only pass.
// ---------------------------------------------------------------------------
__device__ __forceinline__ void jacobi8h(u64 m[28], float d[8]) {
#pragma unroll 1
    for (int sweep = 0; sweep < 8; ++sweep) {
        if (sweep >= 4) {
            u64 acc = 0ULL;
#pragma unroll
            for (int i = 0; i < 28; ++i) acc = f2fma(m[i], m[i], acc);
            float o1, o2; upk2(acc, o1, o2);
            if (__all_sync(0xFFFFFFFFu, o1 + o2 < 1e-4f)) break;
        }
        jacobi_sweep(m, d);
    }
    diag_pass(m, d);
}

// ---------------------------------------------------------------------------
// 8-element sorting network (19 comparators, ascending)
// ---------------------------------------------------------------------------
__device__ __forceinline__ void sort8(float w[8]) {
#define CAS(i, j) { float lo = fminf(w[i], w[j]); float hi = fmaxf(w[i], w[j]); w[i] = lo; w[j] = hi; }
    CAS(0,1) CAS(2,3) CAS(4,5) CAS(6,7)
    CAS(0,2) CAS(1,3) CAS(4,6) CAS(5,7)
    CAS(1,2) CAS(5,6) CAS(0,4) CAS(3,7)
    CAS(1,5) CAS(2,6)
    CAS(1,4) CAS(3,6)
    CAS(2,4) CAS(3,5)
    CAS(3,4)
#undef CAS
}

// ---------------------------------------------------------------------------
// Fused kernel: 384 threads = 3 type-groups x 128 batch elements.
//   group 0: rho     -> full sorted spectrum -> loss assembly + store
//   group 1: pt_a    -> (min, max) via smem
//   group 2: pt_c    -> (min, max) via smem
// One shared input staging serves all three groups.
// ---------------------------------------------------------------------------
__global__ void __launch_bounds__(384)
fused_kernel(const float* __restrict__ rho_vec,
             const int* __restrict__ rank0p, const int* __restrict__ rank1p,
             float* __restrict__ out, int n) {
    __shared__ float sv[128 * 63];
    __shared__ float ex[128][4];   // [t] = {ea_min, ea_max, ec_min, ec_max}

    const int base = blockIdx.x * 128;
    const int rows = min(128, n - base);
    const int total = rows * 63;
    const float* src = rho_vec + (size_t)base * 63;
    for (int i = threadIdx.x; i < total; i += 384) sv[i] = src[i];
    __syncthreads();

    const int tg = threadIdx.x / 128;       // type group (warp-uniform)
    const int t  = threadIdx.x % 128;       // element slot within block
    const int b  = base + t;
    const bool valid = (b < n);
    const int row = valid ? t : 0;          // clamp for __all_sync safety
    const float* v = sv + row * 63;

    u64 m[28];
    float d[8];

    if (tg == 0) {
        build8<0>(v, m, d);
        jacobi8h(m, d);
        sort8(d);
        // d now holds the full ascending spectrum of rho; wait for groups 1,2
        __syncthreads();
        if (valid) {
            const float beta0 = 1.f / (1.f - 8.f * d[0]);
            const float beta1 = 1.f / (1.f - 8.f * d[7]);

            const int n0 = 8 - *rank0p;
            const int n1 = 8 - *rank1p;

            float S0 = 0.f, S1 = 0.f;
#pragma unroll
            for (int i = 0; i < 8; ++i) {
                if (i < n0)      S0 += d[i];     // n0 smallest of w
                if (i >= 8 - n1) S1 += d[i];     // n1 largest  of w
            }

            const float loss0 = beta0 * (S0 - 0.125f * (float)n0) + 0.125f * (float)n0;
            const float loss1 = beta1 * (S1 - 0.125f * (float)n1) + 0.125f * (float)n1;
            const float tsum = loss0 + loss1;
            float loss = tsum * tsum;

            float e;
            e = beta0 * (ex[t][0] - 0.125f) + 0.125f; loss += e * e;  // pt_a dm0
            e = beta0 * (ex[t][2] - 0.125f) + 0.125f; loss += e * e;  // pt_c dm0
            e = beta1 * (ex[t][1] - 0.125f) + 0.125f; loss += e * e;  // pt_a dm1
            e = beta1 * (ex[t][3] - 0.125f) + 0.125f; loss += e * e;  // pt_c dm1

            out[b] = loss;
        }
    } else {
        if (tg == 1) build8<1>(v, m, d);
        else         build8<2>(v, m, d);
        jacobi8h(m, d);
        // only min & max needed
        float mn = d[0], mx = d[0];
#pragma unroll
        for (int i = 1; i < 8; ++i) {
            mn = fminf(mn, d[i]);
            mx = fmaxf(mx, d[i]);
        }
        const int col = (tg - 1) * 2;
        ex[t][col]     = mn;
        ex[t][col + 1] = mx;
        __syncthreads();
    }
}

// ---------------------------------------------------------------------------
// Entry point
// ---------------------------------------------------------------------------
extern "C" void kernel_launch(void* const* d_in, const int* in_sizes, int n_in,
                              void* d_out, int out_size) {
    const float* rho_vec = (const float*)d_in[0];
    const int*   rank0   = (const int*)d_in[1];
    const int*   rank1   = (const int*)d_in[2];
    float*       out     = (float*)d_out;

    const int n = in_sizes[0] / 63;

    dim3 grid((n + 127) / 128);
    fused_kernel<<<grid, 384>>>(rho_vec, rank0, rank1, out, n);
}